// round 11
// baseline (speedup 1.0000x reference)
#include <cuda_runtime.h>
#include <cuda_bf16.h>
#include <cstdint>

#define NA 256
#define NU 1024
#define DD 64
#define NE (NA * NU)

// ---------------- scratch (static __device__, no allocation) ----------------
__device__ __align__(16) float g_ap_sum[NA * DD];
__device__ __align__(16) float g_ue_sum[NU * DD];
__device__ __align__(16) float g_c1[NA * DD];
__device__ __align__(16) float g_c2[NU * DD];
__device__ __align__(16) float g_corr_a[NA * DD];
__device__ __align__(16) float g_corr_u[NU * DD];
// pre-split bf16 weight blobs in ldmatrix-ready swizzled layouts
__device__ __align__(16) unsigned char g_w12h[16384];  // [half][k 0..63][n 0..63]
__device__ __align__(16) unsigned char g_w12l[16384];
__device__ __align__(16) unsigned char g_w3h[16384];   // [k 0..127][n 0..63]
__device__ __align__(16) unsigned char g_w3l[16384];

#define SWZ(x)  ((x) ^ (((x) >> 3) & 0x70))   // 128B-row swizzle

// smem layout (bytes)
#define OFF_EH   0        // E hi bf16 [128][64]
#define OFF_EL   16384    // E lo
#define OFF_WTH  32768    // W12 hi during MMA1 -> T hi after (re-copied per tile)
#define OFF_WTL  49152
#define OFF_W3H  65536
#define OFF_W3L  81920
#define OFF_C1   98304    // 16*64 f32
#define OFF_C2   102400   // 8*64 f32
#define OFF_UE   104448   // 8*64 f32 partial ue sums
#define SMEM_KT  106496

// ---------------- helpers ----------------
__device__ __forceinline__ uint32_t smem_u32(const void* p) {
    uint32_t a;
    asm("{ .reg .u64 t; cvta.to.shared.u64 t, %1; cvt.u32.u64 %0, t; }" : "=r"(a) : "l"(p));
    return a;
}
__device__ __forceinline__ void ldsm_x4(uint32_t* r, uint32_t addr) {
    asm volatile("ldmatrix.sync.aligned.m8n8.x4.shared.b16 {%0,%1,%2,%3}, [%4];"
                 : "=r"(r[0]), "=r"(r[1]), "=r"(r[2]), "=r"(r[3]) : "r"(addr));
}
__device__ __forceinline__ void ldsm_x2t(uint32_t* r, uint32_t addr) {
    asm volatile("ldmatrix.sync.aligned.m8n8.x2.trans.shared.b16 {%0,%1}, [%2];"
                 : "=r"(r[0]), "=r"(r[1]) : "r"(addr));
}
__device__ __forceinline__ void mma_bf16(float* c, const uint32_t* a, const uint32_t* b) {
    asm volatile("mma.sync.aligned.m16n8k16.row.col.f32.bf16.bf16.f32 "
                 "{%0,%1,%2,%3},{%4,%5,%6,%7},{%8,%9},{%0,%1,%2,%3};"
                 : "+f"(c[0]), "+f"(c[1]), "+f"(c[2]), "+f"(c[3])
                 : "r"(a[0]), "r"(a[1]), "r"(a[2]), "r"(a[3]), "r"(b[0]), "r"(b[1]));
}
__device__ __forceinline__ void bsplit(float x, unsigned short& h, unsigned short& l) {
    __nv_bfloat16 hb = __float2bfloat16(x);
    h = __bfloat16_as_ushort(hb);
    l = __bfloat16_as_ushort(__float2bfloat16(x - __bfloat162float(hb)));
}
__device__ __forceinline__ float frelu(float x) { return fmaxf(x, 0.0f); }

// ---------------------------------------------------------------------------
// KP: merged prep. 320 blocks x 256 threads = 81920 threads.
//   - zero ap_sum/ue_sum
//   - c1[a] = b1 + ap_hid[a].W1top ; c2[u] = b2 + ue_hid[u].W2top
//   - build pre-split/swizzled bf16 weight blobs (ids < 16384)
// ---------------------------------------------------------------------------
__global__ void __launch_bounds__(256) kp_prep(
    const float* __restrict__ ap_hid, const float* __restrict__ ue_hid,
    const float* __restrict__ W1, const float* __restrict__ b1,
    const float* __restrict__ W2, const float* __restrict__ b2,
    const float* __restrict__ W3) {
    int id = blockIdx.x * 256 + threadIdx.x;   // 0..81919

    // zero sums (81920 == (NA+NU)*DD exactly)
    if (id < NA * DD) g_ap_sum[id] = 0.0f;
    else g_ue_sum[id - NA * DD] = 0.0f;

    // c1/c2 (ILP-4 accumulators)
    {
        int row = id >> 6, d = id & 63;
        const float *H, *W, *B; float* O;
        if (row < NA) { H = ap_hid + row * DD; W = W1; B = b1; O = g_c1 + row * DD; }
        else { int u = row - NA; H = ue_hid + u * DD; W = W2; B = b2; O = g_c2 + u * DD; }
        float a0 = B[d], a1 = 0.0f, a2 = 0.0f, a3 = 0.0f;
#pragma unroll 4
        for (int k = 0; k < DD; k += 4) {
            a0 += H[k]     * W[(k)     * DD + d];
            a1 += H[k + 1] * W[(k + 1) * DD + d];
            a2 += H[k + 2] * W[(k + 2) * DD + d];
            a3 += H[k + 3] * W[(k + 3) * DD + d];
        }
        O[d] = (a0 + a1) + (a2 + a3);
    }

    // weight blobs
    if (id < 8192) {                 // W12: [half][k][n], k = bottom rows 64..127
        int h = id >> 12;            // 0=ap(W1), 1=ue(W2)
        int r = id & 4095;
        int k = r >> 6, n = r & 63;
        float f = h ? W2[(64 + k) * DD + n] : W1[(64 + k) * DD + n];
        unsigned short hh, ll; bsplit(f, hh, ll);
        int off = h * 8192 + SWZ(k * 128 + n * 2);
        *(unsigned short*)(g_w12h + off) = hh;
        *(unsigned short*)(g_w12l + off) = ll;
    } else if (id < 16384) {         // W3: [k 0..127][n]
        int e = id - 8192;
        int k = e >> 6, n = e & 63;
        float f = W3[k * DD + n];
        unsigned short hh, ll; bsplit(f, hh, ll);
        int off = SWZ(k * 128 + n * 2);
        *(unsigned short*)(g_w3h + off) = hh;
        *(unsigned short*)(g_w3l + off) = ll;
    }
}

// ---------------------------------------------------------------------------
// KT: fused mma.sync kernel. 1024 blocks, each does 2 tiles (16a x 8u each,
// same a0, adjacent u0). 8 warps; warp w owns rows 16w..16w+15.
//   MMA1: C[128x128] = E(h/l) . [W1bot|W2bot](h/l)   (3-term split)
//   epi1: ap=relu(c1+Cap), ue=relu(c2+Cue); T=-(ap+ue) -> bf16 h/l (W12 region);
//         ap_sum via shfl-butterfly + REDG; ue_sum via smem partials + REDG
//   MMA2: D[128x64] = [E|T](h/l) . W3(h/l)  -> direct float2 stores
// ---------------------------------------------------------------------------
__global__ void __launch_bounds__(256, 2) kt_fused(const float* __restrict__ edge,
                                                   float* __restrict__ out) {
    extern __shared__ char smem[];
    uint32_t sb = smem_u32(smem);
    int t = threadIdx.x, w = t >> 5, lane = t & 31;
    int at = blockIdx.x >> 6;          // 0..15
    int upair = blockIdx.x & 63;       // 0..63
    int a0 = at * 16;

    // hoisted: W3 blobs + c1 slice (shared by both tiles)
#pragma unroll
    for (int i = 0; i < 4; ++i) {
        int idx = i * 256 + t;
        ((float4*)(smem + OFF_W3H))[idx] = ((const float4*)g_w3h)[idx];
        ((float4*)(smem + OFF_W3L))[idx] = ((const float4*)g_w3l)[idx];
        ((float*)(smem + OFF_C1))[idx]  = g_c1[a0 * DD + idx];
    }

    int arow = 16 * w + (lane & 15);
    int acol = (lane >> 4) * 16;        // byte col of A k-tile half
    int u_l = lane >> 2, jc = 2 * (lane & 3);
    int aL = 2 * w, aH = 2 * w + 1;
    int r0 = 16 * w + u_l;

#pragma unroll 1
    for (int tile = 0; tile < 2; ++tile) {
        int u0 = upair * 16 + tile * 8;

        // zero ue partials + c2 slice
        ((float*)(smem + OFF_UE))[t] = 0.0f;
        ((float*)(smem + OFF_UE))[t + 256] = 0.0f;
        ((float*)(smem + OFF_C2))[t] = g_c2[u0 * DD + t];
        ((float*)(smem + OFF_C2))[t + 256] = g_c2[u0 * DD + t + 256];
        // W12 blobs (re-copied: region is aliased by T each tile)
#pragma unroll
        for (int i = 0; i < 4; ++i) {
            int idx = i * 256 + t;
            ((float4*)(smem + OFF_WTH))[idx] = ((const float4*)g_w12h)[idx];
            ((float4*)(smem + OFF_WTL))[idx] = ((const float4*)g_w12l)[idx];
        }
        // edge tile: fp32 -> bf16 hi/lo, swizzled
#pragma unroll
        for (int i = 0; i < 8; ++i) {
            int lin = i * 256 + t;          // float4 index
            int row = lin >> 4, c4 = lin & 15;
            size_t g = ((size_t)(a0 + (row >> 3)) * NU + (u0 + (row & 7))) * DD + c4 * 4;
            float4 v = *(const float4*)&edge[g];
            unsigned short h0, l0, h1, l1, h2, l2, h3, l3;
            bsplit(v.x, h0, l0); bsplit(v.y, h1, l1);
            bsplit(v.z, h2, l2); bsplit(v.w, h3, l3);
            int so = SWZ(row * 128 + c4 * 8);
            *(uint2*)(smem + OFF_EH + so) =
                make_uint2((uint32_t)h0 | ((uint32_t)h1 << 16), (uint32_t)h2 | ((uint32_t)h3 << 16));
            *(uint2*)(smem + OFF_EL + so) =
                make_uint2((uint32_t)l0 | ((uint32_t)l1 << 16), (uint32_t)l2 | ((uint32_t)l3 << 16));
        }
        __syncthreads();

        // ---- MMA1 ----
        float acc[16][4];
#pragma unroll
        for (int nt = 0; nt < 16; ++nt)
#pragma unroll
            for (int j = 0; j < 4; ++j) acc[nt][j] = 0.0f;

#pragma unroll
        for (int ks = 0; ks < 4; ++ks) {
            uint32_t ah[4], al[4];
            int ao = SWZ(arow * 128 + ks * 32 + acol);
            ldsm_x4(ah, sb + OFF_EH + ao);
            ldsm_x4(al, sb + OFF_EL + ao);
            int brow = ks * 16 + (lane & 15);
#pragma unroll
            for (int nt = 0; nt < 16; ++nt) {
                uint32_t boff = (uint32_t)((nt >> 3) * 8192 + SWZ(brow * 128 + (nt & 7) * 16));
                uint32_t bh[2], bl[2];
                ldsm_x2t(bh, sb + OFF_WTH + boff);
                ldsm_x2t(bl, sb + OFF_WTL + boff);
                mma_bf16(acc[nt], ah, bh);
                mma_bf16(acc[nt], ah, bl);
                mma_bf16(acc[nt], al, bh);
            }
        }
        __syncthreads();  // W12 fully consumed -> safe to alias as T

        // ---- epilogue 1 ----
        {
            const float* c1s = (const float*)(smem + OFF_C1);
            const float* c2s = (const float*)(smem + OFF_C2);
            float* sue = (float*)(smem + OFF_UE);
#pragma unroll
            for (int nt = 0; nt < 8; ++nt) {
                int col = nt * 8 + jc;
                float vap0 = frelu(c1s[aL * 64 + col]     + acc[nt][0]);
                float vap1 = frelu(c1s[aL * 64 + col + 1] + acc[nt][1]);
                float vap2 = frelu(c1s[aH * 64 + col]     + acc[nt][2]);
                float vap3 = frelu(c1s[aH * 64 + col + 1] + acc[nt][3]);
                float vue0 = frelu(c2s[u_l * 64 + col]     + acc[nt + 8][0]);
                float vue1 = frelu(c2s[u_l * 64 + col + 1] + acc[nt + 8][1]);
                float vue2 = frelu(c2s[u_l * 64 + col]     + acc[nt + 8][2]);
                float vue3 = frelu(c2s[u_l * 64 + col + 1] + acc[nt + 8][3]);
                // T = -(ap+ue), split hi/lo, store (aliases W12 region)
                {
                    unsigned short h0, l0, h1, l1;
                    bsplit(-(vap0 + vue0), h0, l0); bsplit(-(vap1 + vue1), h1, l1);
                    int o = SWZ(r0 * 128 + col * 2);
                    *(uint32_t*)(smem + OFF_WTH + o) = (uint32_t)h0 | ((uint32_t)h1 << 16);
                    *(uint32_t*)(smem + OFF_WTL + o) = (uint32_t)l0 | ((uint32_t)l1 << 16);
                    bsplit(-(vap2 + vue2), h0, l0); bsplit(-(vap3 + vue3), h1, l1);
                    o = SWZ((r0 + 8) * 128 + col * 2);
                    *(uint32_t*)(smem + OFF_WTH + o) = (uint32_t)h0 | ((uint32_t)h1 << 16);
                    *(uint32_t*)(smem + OFF_WTL + o) = (uint32_t)l0 | ((uint32_t)l1 << 16);
                }
                // ue partials into smem (sum over this warp's 2 a's)
                atomicAdd(&sue[u_l * 64 + col],     vue0 + vue2);
                atomicAdd(&sue[u_l * 64 + col + 1], vue1 + vue3);
                // ap sums: butterfly over the 8 u's (lane>>2 axis)
                float s0 = vap0, s1 = vap1, s2 = vap2, s3 = vap3;
#pragma unroll
                for (int d = 4; d < 32; d <<= 1) {
                    s0 += __shfl_xor_sync(0xffffffffu, s0, d);
                    s1 += __shfl_xor_sync(0xffffffffu, s1, d);
                    s2 += __shfl_xor_sync(0xffffffffu, s2, d);
                    s3 += __shfl_xor_sync(0xffffffffu, s3, d);
                }
                if (lane < 4) {
                    atomicAdd(&g_ap_sum[(a0 + aL) * DD + nt * 8 + 2 * lane],     s0);
                    atomicAdd(&g_ap_sum[(a0 + aL) * DD + nt * 8 + 2 * lane + 1], s1);
                    atomicAdd(&g_ap_sum[(a0 + aH) * DD + nt * 8 + 2 * lane],     s2);
                    atomicAdd(&g_ap_sum[(a0 + aH) * DD + nt * 8 + 2 * lane + 1], s3);
                }
            }
        }
        __syncthreads();  // T complete, sue complete

        // ue cross-block REDs (fire-and-forget, overlaps MMA2 issue)
        {
            const float* sue = (const float*)(smem + OFF_UE);
#pragma unroll
            for (int i = 0; i < 2; ++i) {
                int idx = t + i * 256;
                atomicAdd(&g_ue_sum[(u0 + (idx >> 6)) * DD + (idx & 63)], sue[idx]);
            }
        }

        // ---- MMA2 ----
        float acc2[8][4];
#pragma unroll
        for (int nt = 0; nt < 8; ++nt)
#pragma unroll
            for (int j = 0; j < 4; ++j) acc2[nt][j] = 0.0f;

#pragma unroll
        for (int ks = 0; ks < 8; ++ks) {
            uint32_t srcH = (ks < 4) ? OFF_EH : OFF_WTH;
            uint32_t srcL = (ks < 4) ? OFF_EL : OFF_WTL;
            uint32_t ah[4], al[4];
            int ao = SWZ(arow * 128 + (ks & 3) * 32 + acol);
            ldsm_x4(ah, sb + srcH + ao);
            ldsm_x4(al, sb + srcL + ao);
            int brow = ks * 16 + (lane & 15);
#pragma unroll
            for (int nt = 0; nt < 8; ++nt) {
                uint32_t boff = (uint32_t)SWZ(brow * 128 + nt * 16);
                uint32_t bh[2], bl[2];
                ldsm_x2t(bh, sb + OFF_W3H + boff);
                ldsm_x2t(bl, sb + OFF_W3L + boff);
                mma_bf16(acc2[nt], ah, bh);
                mma_bf16(acc2[nt], ah, bl);
                mma_bf16(acc2[nt], al, bh);
            }
        }

        // ---- epilogue 2: direct float2 stores (32B-sector aligned groups) ----
        {
            int uu = u0 + u_l;
            size_t base0 = ((size_t)(a0 + aL) * NU + uu) * DD;
            size_t base1 = ((size_t)(a0 + aH) * NU + uu) * DD;
#pragma unroll
            for (int nt = 0; nt < 8; ++nt) {
                int col = nt * 8 + jc;
                *(float2*)&out[base0 + col] = make_float2(acc2[nt][0], acc2[nt][1]);
                *(float2*)&out[base1 + col] = make_float2(acc2[nt][2], acc2[nt][3]);
            }
        }
        __syncthreads();  // protect E / T(W12) / sue before next tile overwrites
    }
}

// ---------------------------------------------------------------------------
// KC: corr_a[a] = ap_sum[a].W3bot ; corr_u[u] = ue_sum[u].W3bot + b3  (fp32)
// 320 blocks x 256 threads, 4 rows per block, ILP-4.
// ---------------------------------------------------------------------------
__global__ void __launch_bounds__(256) kc_corr(const float* __restrict__ W3,
                                               const float* __restrict__ b3) {
    int row = blockIdx.x * 4 + (threadIdx.x >> 6);
    int d = threadIdx.x & 63;
    const float* S; float* O; float base;
    if (row < NA) { S = g_ap_sum + row * DD; O = g_corr_a + row * DD; base = 0.0f; }
    else { int u = row - NA; S = g_ue_sum + u * DD; O = g_corr_u + u * DD; base = b3[d]; }
    float a0 = base, a1 = 0.0f, a2 = 0.0f, a3 = 0.0f;
#pragma unroll 4
    for (int k = 0; k < DD; k += 4) {
        a0 += S[k]     * W3[(64 + k)     * DD + d];
        a1 += S[k + 1] * W3[(64 + k + 1) * DD + d];
        a2 += S[k + 2] * W3[(64 + k + 2) * DD + d];
        a3 += S[k + 3] * W3[(64 + k + 3) * DD + d];
    }
    O[d] = (a0 + a1) + (a2 + a3);
}

// ---------------------------------------------------------------------------
// KF: out += corr_a[a] + corr_u[u]   (b3 folded into corr_u)
// ---------------------------------------------------------------------------
__global__ void __launch_bounds__(256) kf_final(float* __restrict__ out) {
    int t0 = blockIdx.x * 256 + threadIdx.x;
#pragma unroll
    for (int i = 0; i < 4; ++i) {
        int fi = t0 + i * 1048576;
        int m = fi >> 4;
        int dq = (fi & 15) * 4;
        int a = m >> 10, u = m & 1023;
        float4 o = ((float4*)out)[fi];
        float4 ca = *(const float4*)&g_corr_a[a * DD + dq];
        float4 cu = *(const float4*)&g_corr_u[u * DD + dq];
        o.x += ca.x + cu.x;
        o.y += ca.y + cu.y;
        o.z += ca.z + cu.z;
        o.w += ca.w + cu.w;
        ((float4*)out)[fi] = o;
    }
}

// ---------------------------------------------------------------------------
extern "C" void kernel_launch(void* const* d_in, const int* in_sizes, int n_in,
                              void* d_out, int out_size) {
    const float* ap_hid = (const float*)d_in[0];
    const float* ue_hid = (const float*)d_in[1];
    const float* edge   = (const float*)d_in[2];
    const float* W1     = (const float*)d_in[3];
    const float* b1     = (const float*)d_in[4];
    const float* W2     = (const float*)d_in[5];
    const float* b2     = (const float*)d_in[6];
    const float* W3     = (const float*)d_in[7];
    const float* b3     = (const float*)d_in[8];
    float* out = (float*)d_out;

    cudaFuncSetAttribute(kt_fused, cudaFuncAttributeMaxDynamicSharedMemorySize, SMEM_KT);

    kp_prep<<<320, 256>>>(ap_hid, ue_hid, W1, b1, W2, b2, W3);
    kt_fused<<<1024, 256, SMEM_KT>>>(edge, out);
    kc_corr<<<320, 256>>>(W3, b3);
    kf_final<<<4096, 256>>>(out);
}

// round 12
// speedup vs baseline: 1.4693x; 1.4693x over previous
#include <cuda_runtime.h>
#include <cuda_bf16.h>
#include <cstdint>

#define NA 256
#define NU 1024
#define DD 64
#define NE (NA * NU)

// ---------------- scratch (static __device__, no allocation) ----------------
__device__ __align__(16) float g_ap_sum[NA * DD];
__device__ __align__(16) float g_ue_sum[NU * DD];
__device__ __align__(16) float g_c1[NA * DD];
__device__ __align__(16) float g_c2[NU * DD];
__device__ __align__(16) float g_corr_a[NA * DD];
__device__ __align__(16) float g_corr_u[NU * DD];
// pre-split bf16 weight blobs in ldmatrix-ready swizzled layouts
__device__ __align__(16) unsigned char g_w12h[16384];  // [half][k 0..63][n 0..63]
__device__ __align__(16) unsigned char g_w12l[16384];
__device__ __align__(16) unsigned char g_w3h[16384];   // [k 0..127][n 0..63]
__device__ __align__(16) unsigned char g_w3l[16384];

#define SWZ(x)  ((x) ^ (((x) >> 3) & 0x70))   // 128B-row swizzle
#define SWZO(x) ((x) ^ (((x) >> 4) & 0x70))   // 256B-row swizzle (fp32 out staging)

// smem layout (bytes)
#define OFF_EH   0        // E hi bf16 [128][64]  (aliased by fp32 out staging later)
#define OFF_EL   16384    // E lo
#define OFF_WTH  32768    // W12 hi during MMA1 -> T hi after
#define OFF_WTL  49152
#define OFF_W3H  65536
#define OFF_W3L  81920
#define OFF_C1   98304    // 16*64 f32
#define OFF_C2   102400   // 8*64 f32
#define OFF_UE   104448   // 8*64 f32 partial ue sums
#define SMEM_KT  106496

// ---------------- helpers ----------------
__device__ __forceinline__ uint32_t smem_u32(const void* p) {
    uint32_t a;
    asm("{ .reg .u64 t; cvta.to.shared.u64 t, %1; cvt.u32.u64 %0, t; }" : "=r"(a) : "l"(p));
    return a;
}
__device__ __forceinline__ void ldsm_x4(uint32_t* r, uint32_t addr) {
    asm volatile("ldmatrix.sync.aligned.m8n8.x4.shared.b16 {%0,%1,%2,%3}, [%4];"
                 : "=r"(r[0]), "=r"(r[1]), "=r"(r[2]), "=r"(r[3]) : "r"(addr));
}
__device__ __forceinline__ void ldsm_x4t(uint32_t* r, uint32_t addr) {
    asm volatile("ldmatrix.sync.aligned.m8n8.x4.trans.shared.b16 {%0,%1,%2,%3}, [%4];"
                 : "=r"(r[0]), "=r"(r[1]), "=r"(r[2]), "=r"(r[3]) : "r"(addr));
}
__device__ __forceinline__ void mma_bf16(float* c, const uint32_t* a, const uint32_t* b) {
    asm volatile("mma.sync.aligned.m16n8k16.row.col.f32.bf16.bf16.f32 "
                 "{%0,%1,%2,%3},{%4,%5,%6,%7},{%8,%9},{%0,%1,%2,%3};"
                 : "+f"(c[0]), "+f"(c[1]), "+f"(c[2]), "+f"(c[3])
                 : "r"(a[0]), "r"(a[1]), "r"(a[2]), "r"(a[3]), "r"(b[0]), "r"(b[1]));
}
__device__ __forceinline__ void bsplit(float x, unsigned short& h, unsigned short& l) {
    __nv_bfloat16 hb = __float2bfloat16(x);
    h = __bfloat16_as_ushort(hb);
    l = __bfloat16_as_ushort(__float2bfloat16(x - __bfloat162float(hb)));
}
__device__ __forceinline__ float frelu(float x) { return fmaxf(x, 0.0f); }

// ---------------------------------------------------------------------------
// KP: merged prep. 320 blocks x 256 threads = 81920 threads.
// ---------------------------------------------------------------------------
__global__ void __launch_bounds__(256) kp_prep(
    const float* __restrict__ ap_hid, const float* __restrict__ ue_hid,
    const float* __restrict__ W1, const float* __restrict__ b1,
    const float* __restrict__ W2, const float* __restrict__ b2,
    const float* __restrict__ W3) {
    int id = blockIdx.x * 256 + threadIdx.x;   // 0..81919

    // zero sums (81920 == (NA+NU)*DD exactly)
    if (id < NA * DD) g_ap_sum[id] = 0.0f;
    else g_ue_sum[id - NA * DD] = 0.0f;

    // c1/c2 (ILP-4 accumulators)
    {
        int row = id >> 6, d = id & 63;
        const float *H, *W, *B; float* O;
        if (row < NA) { H = ap_hid + row * DD; W = W1; B = b1; O = g_c1 + row * DD; }
        else { int u = row - NA; H = ue_hid + u * DD; W = W2; B = b2; O = g_c2 + u * DD; }
        float a0 = B[d], a1 = 0.0f, a2 = 0.0f, a3 = 0.0f;
#pragma unroll 4
        for (int k = 0; k < DD; k += 4) {
            a0 += H[k]     * W[(k)     * DD + d];
            a1 += H[k + 1] * W[(k + 1) * DD + d];
            a2 += H[k + 2] * W[(k + 2) * DD + d];
            a3 += H[k + 3] * W[(k + 3) * DD + d];
        }
        O[d] = (a0 + a1) + (a2 + a3);
    }

    // weight blobs
    if (id < 8192) {                 // W12: [half][k][n], k = bottom rows 64..127
        int h = id >> 12;            // 0=ap(W1), 1=ue(W2)
        int r = id & 4095;
        int k = r >> 6, n = r & 63;
        float f = h ? W2[(64 + k) * DD + n] : W1[(64 + k) * DD + n];
        unsigned short hh, ll; bsplit(f, hh, ll);
        int off = h * 8192 + SWZ(k * 128 + n * 2);
        *(unsigned short*)(g_w12h + off) = hh;
        *(unsigned short*)(g_w12l + off) = ll;
    } else if (id < 16384) {         // W3: [k 0..127][n]
        int e = id - 8192;
        int k = e >> 6, n = e & 63;
        float f = W3[k * DD + n];
        unsigned short hh, ll; bsplit(f, hh, ll);
        int off = SWZ(k * 128 + n * 2);
        *(unsigned short*)(g_w3h + off) = hh;
        *(unsigned short*)(g_w3l + off) = ll;
    }
}

// ---------------------------------------------------------------------------
// KT: fused mma.sync kernel. 2048 blocks, ONE 16a x 8u tile each (R6 structure).
// 8 warps; warp w owns rows 16w..16w+15 (a = {2w,2w+1}, u = row&7).
//   MMA1: C[128x128] = E(h/l) . [W1bot|W2bot](h/l)   (3-term split)
//   epi1: ap=relu(c1+Cap), ue=relu(c2+Cue); T=-(ap+ue) -> bf16 h/l (W12 region);
//         ap_sum via shfl-butterfly + REDG; ue_sum via smem partials + REDG
//   MMA2: D[128x64] = [E|T](h/l) . W3(h/l)  -> staged -> coalesced float4 out
// B-fragments loaded 2 n-tiles at a time via ldmatrix.x4.trans.
// ---------------------------------------------------------------------------
__global__ void __launch_bounds__(256, 2) kt_fused(const float* __restrict__ edge,
                                                   float* __restrict__ out) {
    extern __shared__ char smem[];
    uint32_t sb = smem_u32(smem);
    int t = threadIdx.x, w = t >> 5, lane = t & 31;
    int at = blockIdx.x >> 7, ut = blockIdx.x & 127;
    int a0 = at * 16, u0 = ut * 8;

    // zero ue partials
    ((float*)(smem + OFF_UE))[t] = 0.0f;
    ((float*)(smem + OFF_UE))[t + 256] = 0.0f;
    // c1/c2 slices
#pragma unroll
    for (int i = 0; i < 4; ++i)
        ((float*)(smem + OFF_C1))[i * 256 + t] = g_c1[a0 * DD + i * 256 + t];
    ((float*)(smem + OFF_C2))[t] = g_c2[u0 * DD + t];
    ((float*)(smem + OFF_C2))[t + 256] = g_c2[u0 * DD + t + 256];
    // weight blobs (already swizzled) — straight float4 copies
#pragma unroll
    for (int i = 0; i < 4; ++i) {
        int idx = i * 256 + t;
        ((float4*)(smem + OFF_WTH))[idx] = ((const float4*)g_w12h)[idx];
        ((float4*)(smem + OFF_WTL))[idx] = ((const float4*)g_w12l)[idx];
        ((float4*)(smem + OFF_W3H))[idx] = ((const float4*)g_w3h)[idx];
        ((float4*)(smem + OFF_W3L))[idx] = ((const float4*)g_w3l)[idx];
    }
    // edge tile: fp32 -> bf16 hi/lo, swizzled
#pragma unroll
    for (int i = 0; i < 8; ++i) {
        int lin = i * 256 + t;          // float4 index
        int row = lin >> 4, c4 = lin & 15;
        size_t g = ((size_t)(a0 + (row >> 3)) * NU + (u0 + (row & 7))) * DD + c4 * 4;
        float4 v = *(const float4*)&edge[g];
        unsigned short h0, l0, h1, l1, h2, l2, h3, l3;
        bsplit(v.x, h0, l0); bsplit(v.y, h1, l1);
        bsplit(v.z, h2, l2); bsplit(v.w, h3, l3);
        int so = SWZ(row * 128 + c4 * 8);
        *(uint2*)(smem + OFF_EH + so) =
            make_uint2((uint32_t)h0 | ((uint32_t)h1 << 16), (uint32_t)h2 | ((uint32_t)h3 << 16));
        *(uint2*)(smem + OFF_EL + so) =
            make_uint2((uint32_t)l0 | ((uint32_t)l1 << 16), (uint32_t)l2 | ((uint32_t)l3 << 16));
    }
    __syncthreads();

    int arow = 16 * w + (lane & 15);
    int acol = (lane >> 4) * 16;        // byte col of A k-tile half
    int ntsel = lane >> 4;              // 0/1: which of the 2 x4t n-tiles this lane addresses

    // ---- MMA1 ----
    float acc[16][4];
#pragma unroll
    for (int nt = 0; nt < 16; ++nt)
#pragma unroll
        for (int j = 0; j < 4; ++j) acc[nt][j] = 0.0f;

#pragma unroll
    for (int ks = 0; ks < 4; ++ks) {
        uint32_t ah[4], al[4];
        int ao = SWZ(arow * 128 + ks * 32 + acol);
        ldsm_x4(ah, sb + OFF_EH + ao);
        ldsm_x4(al, sb + OFF_EL + ao);
        int brow = ks * 16 + (lane & 15);
#pragma unroll
        for (int nt2 = 0; nt2 < 8; ++nt2) {
            int ntp = 2 * nt2 + ntsel;   // per-lane n-tile index for x4t
            uint32_t boff = (uint32_t)((ntp >> 3) * 8192 + SWZ(brow * 128 + (ntp & 7) * 16));
            uint32_t bh[4], bl[4];
            ldsm_x4t(bh, sb + OFF_WTH + boff);
            ldsm_x4t(bl, sb + OFF_WTL + boff);
            mma_bf16(acc[2 * nt2],     ah, bh);
            mma_bf16(acc[2 * nt2],     ah, bl);
            mma_bf16(acc[2 * nt2],     al, bh);
            mma_bf16(acc[2 * nt2 + 1], ah, bh + 2);
            mma_bf16(acc[2 * nt2 + 1], ah, bl + 2);
            mma_bf16(acc[2 * nt2 + 1], al, bh + 2);
        }
    }
    __syncthreads();  // W12 fully consumed -> safe to alias as T

    // ---- epilogue 1 ----
    int u_l = lane >> 2, jc = 2 * (lane & 3);
    int aL = 2 * w, aH = 2 * w + 1;
    int r0 = 16 * w + u_l;
    {
        const float* c1s = (const float*)(smem + OFF_C1);
        const float* c2s = (const float*)(smem + OFF_C2);
        float* sue = (float*)(smem + OFF_UE);
#pragma unroll
        for (int nt = 0; nt < 8; ++nt) {
            int col = nt * 8 + jc;
            float vap0 = frelu(c1s[aL * 64 + col]     + acc[nt][0]);
            float vap1 = frelu(c1s[aL * 64 + col + 1] + acc[nt][1]);
            float vap2 = frelu(c1s[aH * 64 + col]     + acc[nt][2]);
            float vap3 = frelu(c1s[aH * 64 + col + 1] + acc[nt][3]);
            float vue0 = frelu(c2s[u_l * 64 + col]     + acc[nt + 8][0]);
            float vue1 = frelu(c2s[u_l * 64 + col + 1] + acc[nt + 8][1]);
            float vue2 = frelu(c2s[u_l * 64 + col]     + acc[nt + 8][2]);
            float vue3 = frelu(c2s[u_l * 64 + col + 1] + acc[nt + 8][3]);
            // T = -(ap+ue), split hi/lo, store (aliases W12 region)
            {
                unsigned short h0, l0, h1, l1;
                bsplit(-(vap0 + vue0), h0, l0); bsplit(-(vap1 + vue1), h1, l1);
                int o = SWZ(r0 * 128 + col * 2);
                *(uint32_t*)(smem + OFF_WTH + o) = (uint32_t)h0 | ((uint32_t)h1 << 16);
                *(uint32_t*)(smem + OFF_WTL + o) = (uint32_t)l0 | ((uint32_t)l1 << 16);
                bsplit(-(vap2 + vue2), h0, l0); bsplit(-(vap3 + vue3), h1, l1);
                o = SWZ((r0 + 8) * 128 + col * 2);
                *(uint32_t*)(smem + OFF_WTH + o) = (uint32_t)h0 | ((uint32_t)h1 << 16);
                *(uint32_t*)(smem + OFF_WTL + o) = (uint32_t)l0 | ((uint32_t)l1 << 16);
            }
            // ue partials into smem (sum over this warp's 2 a's)
            atomicAdd(&sue[u_l * 64 + col],     vue0 + vue2);
            atomicAdd(&sue[u_l * 64 + col + 1], vue1 + vue3);
            // ap sums: butterfly over the 8 u's (lane>>2 axis)
            float s0 = vap0, s1 = vap1, s2 = vap2, s3 = vap3;
#pragma unroll
            for (int d = 4; d < 32; d <<= 1) {
                s0 += __shfl_xor_sync(0xffffffffu, s0, d);
                s1 += __shfl_xor_sync(0xffffffffu, s1, d);
                s2 += __shfl_xor_sync(0xffffffffu, s2, d);
                s3 += __shfl_xor_sync(0xffffffffu, s3, d);
            }
            if (lane < 4) {
                atomicAdd(&g_ap_sum[(a0 + aL) * DD + nt * 8 + 2 * lane],     s0);
                atomicAdd(&g_ap_sum[(a0 + aL) * DD + nt * 8 + 2 * lane + 1], s1);
                atomicAdd(&g_ap_sum[(a0 + aH) * DD + nt * 8 + 2 * lane],     s2);
                atomicAdd(&g_ap_sum[(a0 + aH) * DD + nt * 8 + 2 * lane + 1], s3);
            }
        }
    }
    __syncthreads();  // T complete (cross-lane ldmatrix), sue complete

    // ue cross-block REDs (fire-and-forget, overlaps MMA2 issue)
    {
        const float* sue = (const float*)(smem + OFF_UE);
#pragma unroll
        for (int i = 0; i < 2; ++i) {
            int idx = t + i * 256;
            atomicAdd(&g_ue_sum[(u0 + (idx >> 6)) * DD + (idx & 63)], sue[idx]);
        }
    }

    // ---- MMA2 ----
    float acc2[8][4];
#pragma unroll
    for (int nt = 0; nt < 8; ++nt)
#pragma unroll
        for (int j = 0; j < 4; ++j) acc2[nt][j] = 0.0f;

#pragma unroll
    for (int ks = 0; ks < 8; ++ks) {
        uint32_t srcH = (ks < 4) ? OFF_EH : OFF_WTH;
        uint32_t srcL = (ks < 4) ? OFF_EL : OFF_WTL;
        uint32_t ah[4], al[4];
        int ao = SWZ(arow * 128 + (ks & 3) * 32 + acol);
        ldsm_x4(ah, sb + srcH + ao);
        ldsm_x4(al, sb + srcL + ao);
        int brow = ks * 16 + (lane & 15);
#pragma unroll
        for (int nt2 = 0; nt2 < 4; ++nt2) {
            int ntp = 2 * nt2 + ntsel;
            uint32_t boff = (uint32_t)SWZ(brow * 128 + ntp * 16);
            uint32_t bh[4], bl[4];
            ldsm_x4t(bh, sb + OFF_W3H + boff);
            ldsm_x4t(bl, sb + OFF_W3L + boff);
            mma_bf16(acc2[2 * nt2],     ah, bh);
            mma_bf16(acc2[2 * nt2],     ah, bl);
            mma_bf16(acc2[2 * nt2],     al, bh);
            mma_bf16(acc2[2 * nt2 + 1], ah, bh + 2);
            mma_bf16(acc2[2 * nt2 + 1], ah, bl + 2);
            mma_bf16(acc2[2 * nt2 + 1], al, bh + 2);
        }
    }
    __syncthreads();  // E/T consumed -> stage output into OFF_EH region

    // ---- epilogue 2: stage + coalesced write ----
    {
#pragma unroll
        for (int nt = 0; nt < 8; ++nt) {
            int col = nt * 8 + jc;
            *(float2*)(smem + OFF_EH + SWZO(r0 * 256 + col * 4)) =
                make_float2(acc2[nt][0], acc2[nt][1]);
            *(float2*)(smem + OFF_EH + SWZO((r0 + 8) * 256 + col * 4)) =
                make_float2(acc2[nt][2], acc2[nt][3]);
        }
    }
    __syncthreads();
#pragma unroll
    for (int i = 0; i < 8; ++i) {
        int lin = i * 256 + t;
        int row = lin >> 4, c4 = lin & 15;
        float4 v = *(float4*)(smem + OFF_EH + SWZO(row * 256 + c4 * 16));
        size_t g = ((size_t)(a0 + (row >> 3)) * NU + (u0 + (row & 7))) * DD + c4 * 4;
        *(float4*)&out[g] = v;
    }
}

// ---------------------------------------------------------------------------
// KC: corr_a[a] = ap_sum[a].W3bot ; corr_u[u] = ue_sum[u].W3bot + b3  (fp32)
// 320 blocks x 256 threads, 4 rows per block, ILP-4.
// ---------------------------------------------------------------------------
__global__ void __launch_bounds__(256) kc_corr(const float* __restrict__ W3,
                                               const float* __restrict__ b3) {
    int row = blockIdx.x * 4 + (threadIdx.x >> 6);
    int d = threadIdx.x & 63;
    const float* S; float* O; float base;
    if (row < NA) { S = g_ap_sum + row * DD; O = g_corr_a + row * DD; base = 0.0f; }
    else { int u = row - NA; S = g_ue_sum + u * DD; O = g_corr_u + u * DD; base = b3[d]; }
    float a0 = base, a1 = 0.0f, a2 = 0.0f, a3 = 0.0f;
#pragma unroll 4
    for (int k = 0; k < DD; k += 4) {
        a0 += S[k]     * W3[(64 + k)     * DD + d];
        a1 += S[k + 1] * W3[(64 + k + 1) * DD + d];
        a2 += S[k + 2] * W3[(64 + k + 2) * DD + d];
        a3 += S[k + 3] * W3[(64 + k + 3) * DD + d];
    }
    O[d] = (a0 + a1) + (a2 + a3);
}

// ---------------------------------------------------------------------------
// KF: out += corr_a[a] + corr_u[u]   (b3 folded into corr_u)
// ---------------------------------------------------------------------------
__global__ void __launch_bounds__(256) kf_final(float* __restrict__ out) {
    int t0 = blockIdx.x * 256 + threadIdx.x;
#pragma unroll
    for (int i = 0; i < 4; ++i) {
        int fi = t0 + i * 1048576;
        int m = fi >> 4;
        int dq = (fi & 15) * 4;
        int a = m >> 10, u = m & 1023;
        float4 o = ((float4*)out)[fi];
        float4 ca = *(const float4*)&g_corr_a[a * DD + dq];
        float4 cu = *(const float4*)&g_corr_u[u * DD + dq];
        o.x += ca.x + cu.x;
        o.y += ca.y + cu.y;
        o.z += ca.z + cu.z;
        o.w += ca.w + cu.w;
        ((float4*)out)[fi] = o;
    }
}

// ---------------------------------------------------------------------------
extern "C" void kernel_launch(void* const* d_in, const int* in_sizes, int n_in,
                              void* d_out, int out_size) {
    const float* ap_hid = (const float*)d_in[0];
    const float* ue_hid = (const float*)d_in[1];
    const float* edge   = (const float*)d_in[2];
    const float* W1     = (const float*)d_in[3];
    const float* b1     = (const float*)d_in[4];
    const float* W2     = (const float*)d_in[5];
    const float* b2     = (const float*)d_in[6];
    const float* W3     = (const float*)d_in[7];
    const float* b3     = (const float*)d_in[8];
    float* out = (float*)d_out;

    cudaFuncSetAttribute(kt_fused, cudaFuncAttributeMaxDynamicSharedMemorySize, SMEM_KT);

    kp_prep<<<320, 256>>>(ap_hid, ue_hid, W1, b1, W2, b2, W3);
    kt_fused<<<2048, 256, SMEM_KT>>>(edge, out);
    kc_corr<<<320, 256>>>(W3, b3);
    kf_final<<<4096, 256>>>(out);
}

// round 13
// speedup vs baseline: 1.6942x; 1.1531x over previous
#include <cuda_runtime.h>
#include <cuda_bf16.h>
#include <cstdint>

#define NA 256
#define NU 1024
#define DD 64
#define NE (NA * NU)

// ---------------- scratch (static __device__, no allocation) ----------------
__device__ __align__(16) float g_ap_sum[NA * DD];
__device__ __align__(16) float g_ue_sum[NU * DD];
__device__ __align__(16) float g_c1[NA * DD];
__device__ __align__(16) float g_c2[NU * DD];
__device__ __align__(16) float g_corr_a[NA * DD];
__device__ __align__(16) float g_corr_u[NU * DD];
// pre-split bf16 weight blobs in ldmatrix-ready swizzled layouts (weights keep hi+lo)
__device__ __align__(16) unsigned char g_w12h[16384];  // [half][k 0..63][n 0..63]
__device__ __align__(16) unsigned char g_w12l[16384];
__device__ __align__(16) unsigned char g_w3h[16384];   // [k 0..127][n 0..63]
__device__ __align__(16) unsigned char g_w3l[16384];

#define SWZ(x)  ((x) ^ (((x) >> 3) & 0x70))   // 128B-row swizzle
#define SWZO(x) ((x) ^ (((x) >> 4) & 0x70))   // 256B-row swizzle (fp32 out staging)

// smem layout (bytes) — E kept as bf16-hi ONLY (2-term split)
#define OFF_EH   0        // E hi bf16 [128][64]  (aliased by out staging later)
#define OFF_WTH  16384    // W12 hi during MMA1 -> T (bf16, hi only) after
#define OFF_WTL  32768    // W12 lo during MMA1 (dead after)
#define OFF_W3H  49152
#define OFF_W3L  65536
#define OFF_C1   81920    // 16*64 f32
#define OFF_C2   86016    // 8*64 f32
#define OFF_UE   88064    // 8*64 f32 partial ue sums
#define SMEM_KT  90112

// ---------------- helpers ----------------
__device__ __forceinline__ uint32_t smem_u32(const void* p) {
    uint32_t a;
    asm("{ .reg .u64 t; cvta.to.shared.u64 t, %1; cvt.u32.u64 %0, t; }" : "=r"(a) : "l"(p));
    return a;
}
__device__ __forceinline__ void ldsm_x4(uint32_t* r, uint32_t addr) {
    asm volatile("ldmatrix.sync.aligned.m8n8.x4.shared.b16 {%0,%1,%2,%3}, [%4];"
                 : "=r"(r[0]), "=r"(r[1]), "=r"(r[2]), "=r"(r[3]) : "r"(addr));
}
__device__ __forceinline__ void ldsm_x4t(uint32_t* r, uint32_t addr) {
    asm volatile("ldmatrix.sync.aligned.m8n8.x4.trans.shared.b16 {%0,%1,%2,%3}, [%4];"
                 : "=r"(r[0]), "=r"(r[1]), "=r"(r[2]), "=r"(r[3]) : "r"(addr));
}
__device__ __forceinline__ void mma_bf16(float* c, const uint32_t* a, const uint32_t* b) {
    asm volatile("mma.sync.aligned.m16n8k16.row.col.f32.bf16.bf16.f32 "
                 "{%0,%1,%2,%3},{%4,%5,%6,%7},{%8,%9},{%0,%1,%2,%3};"
                 : "+f"(c[0]), "+f"(c[1]), "+f"(c[2]), "+f"(c[3])
                 : "r"(a[0]), "r"(a[1]), "r"(a[2]), "r"(a[3]), "r"(b[0]), "r"(b[1]));
}
__device__ __forceinline__ void bsplit(float x, unsigned short& h, unsigned short& l) {
    __nv_bfloat16 hb = __float2bfloat16(x);
    h = __bfloat16_as_ushort(hb);
    l = __bfloat16_as_ushort(__float2bfloat16(x - __bfloat162float(hb)));
}
__device__ __forceinline__ uint32_t pack_bf16(float a, float b) {
    __nv_bfloat162 v = __float22bfloat162_rn(make_float2(a, b));  // low=a, high=b
    return *(uint32_t*)&v;
}
__device__ __forceinline__ float frelu(float x) { return fmaxf(x, 0.0f); }

// ---------------------------------------------------------------------------
// KP: merged prep. 320 blocks x 256 threads = 81920 threads.
// ---------------------------------------------------------------------------
__global__ void __launch_bounds__(256) kp_prep(
    const float* __restrict__ ap_hid, const float* __restrict__ ue_hid,
    const float* __restrict__ W1, const float* __restrict__ b1,
    const float* __restrict__ W2, const float* __restrict__ b2,
    const float* __restrict__ W3) {
    int id = blockIdx.x * 256 + threadIdx.x;   // 0..81919

    // zero sums (81920 == (NA+NU)*DD exactly)
    if (id < NA * DD) g_ap_sum[id] = 0.0f;
    else g_ue_sum[id - NA * DD] = 0.0f;

    // c1/c2 (ILP-4 accumulators)
    {
        int row = id >> 6, d = id & 63;
        const float *H, *W, *B; float* O;
        if (row < NA) { H = ap_hid + row * DD; W = W1; B = b1; O = g_c1 + row * DD; }
        else { int u = row - NA; H = ue_hid + u * DD; W = W2; B = b2; O = g_c2 + u * DD; }
        float a0 = B[d], a1 = 0.0f, a2 = 0.0f, a3 = 0.0f;
#pragma unroll 4
        for (int k = 0; k < DD; k += 4) {
            a0 += H[k]     * W[(k)     * DD + d];
            a1 += H[k + 1] * W[(k + 1) * DD + d];
            a2 += H[k + 2] * W[(k + 2) * DD + d];
            a3 += H[k + 3] * W[(k + 3) * DD + d];
        }
        O[d] = (a0 + a1) + (a2 + a3);
    }

    // weight blobs (weights keep hi+lo split)
    if (id < 8192) {                 // W12: [half][k][n], k = bottom rows 64..127
        int h = id >> 12;            // 0=ap(W1), 1=ue(W2)
        int r = id & 4095;
        int k = r >> 6, n = r & 63;
        float f = h ? W2[(64 + k) * DD + n] : W1[(64 + k) * DD + n];
        unsigned short hh, ll; bsplit(f, hh, ll);
        int off = h * 8192 + SWZ(k * 128 + n * 2);
        *(unsigned short*)(g_w12h + off) = hh;
        *(unsigned short*)(g_w12l + off) = ll;
    } else if (id < 16384) {         // W3: [k 0..127][n]
        int e = id - 8192;
        int k = e >> 6, n = e & 63;
        float f = W3[k * DD + n];
        unsigned short hh, ll; bsplit(f, hh, ll);
        int off = SWZ(k * 128 + n * 2);
        *(unsigned short*)(g_w3h + off) = hh;
        *(unsigned short*)(g_w3l + off) = ll;
    }
}

// ---------------------------------------------------------------------------
// KT: fused mma.sync kernel. 2048 blocks, ONE 16a x 8u tile each.
// 2-term split: E/T as bf16-hi only; weights hi+lo.
//   MMA1: C[128x128] = Eh . (W12h + W12l)
//   epi1: ap=relu(c1+Cap), ue=relu(c2+Cue); T=-(ap+ue) -> bf16 (WTH region);
//         ap_sum via shfl-butterfly + REDG; ue_sum via smem partials + REDG
//   MMA2: D[128x64] = [Eh|Th] . (W3h + W3l)  -> staged -> coalesced float4 out
// ---------------------------------------------------------------------------
__global__ void __launch_bounds__(256, 2) kt_fused(const float* __restrict__ edge,
                                                   float* __restrict__ out) {
    extern __shared__ char smem[];
    uint32_t sb = smem_u32(smem);
    int t = threadIdx.x, w = t >> 5, lane = t & 31;
    int at = blockIdx.x >> 7, ut = blockIdx.x & 127;
    int a0 = at * 16, u0 = ut * 8;

    // zero ue partials
    ((float*)(smem + OFF_UE))[t] = 0.0f;
    ((float*)(smem + OFF_UE))[t + 256] = 0.0f;
    // c1/c2 slices
#pragma unroll
    for (int i = 0; i < 4; ++i)
        ((float*)(smem + OFF_C1))[i * 256 + t] = g_c1[a0 * DD + i * 256 + t];
    ((float*)(smem + OFF_C2))[t] = g_c2[u0 * DD + t];
    ((float*)(smem + OFF_C2))[t + 256] = g_c2[u0 * DD + t + 256];
    // weight blobs (already swizzled) — straight float4 copies
#pragma unroll
    for (int i = 0; i < 4; ++i) {
        int idx = i * 256 + t;
        ((float4*)(smem + OFF_WTH))[idx] = ((const float4*)g_w12h)[idx];
        ((float4*)(smem + OFF_WTL))[idx] = ((const float4*)g_w12l)[idx];
        ((float4*)(smem + OFF_W3H))[idx] = ((const float4*)g_w3h)[idx];
        ((float4*)(smem + OFF_W3L))[idx] = ((const float4*)g_w3l)[idx];
    }
    // edge tile: fp32 -> bf16 hi only, swizzled
#pragma unroll
    for (int i = 0; i < 8; ++i) {
        int lin = i * 256 + t;          // float4 index
        int row = lin >> 4, c4 = lin & 15;
        size_t g = ((size_t)(a0 + (row >> 3)) * NU + (u0 + (row & 7))) * DD + c4 * 4;
        float4 v = *(const float4*)&edge[g];
        int so = SWZ(row * 128 + c4 * 8);
        *(uint2*)(smem + OFF_EH + so) = make_uint2(pack_bf16(v.x, v.y), pack_bf16(v.z, v.w));
    }
    __syncthreads();

    int arow = 16 * w + (lane & 15);
    int acol = (lane >> 4) * 16;        // byte col of A k-tile half
    int ntsel = lane >> 4;              // 0/1: which of the 2 x4t n-tiles this lane addresses

    // ---- MMA1 ----
    float acc[16][4];
#pragma unroll
    for (int nt = 0; nt < 16; ++nt)
#pragma unroll
        for (int j = 0; j < 4; ++j) acc[nt][j] = 0.0f;

#pragma unroll
    for (int ks = 0; ks < 4; ++ks) {
        uint32_t ah[4];
        int ao = SWZ(arow * 128 + ks * 32 + acol);
        ldsm_x4(ah, sb + OFF_EH + ao);
        int brow = ks * 16 + (lane & 15);
#pragma unroll
        for (int nt2 = 0; nt2 < 8; ++nt2) {
            int ntp = 2 * nt2 + ntsel;   // per-lane n-tile index for x4t
            uint32_t boff = (uint32_t)((ntp >> 3) * 8192 + SWZ(brow * 128 + (ntp & 7) * 16));
            uint32_t bh[4], bl[4];
            ldsm_x4t(bh, sb + OFF_WTH + boff);
            ldsm_x4t(bl, sb + OFF_WTL + boff);
            mma_bf16(acc[2 * nt2],     ah, bh);
            mma_bf16(acc[2 * nt2],     ah, bl);
            mma_bf16(acc[2 * nt2 + 1], ah, bh + 2);
            mma_bf16(acc[2 * nt2 + 1], ah, bl + 2);
        }
    }
    __syncthreads();  // W12 fully consumed -> safe to alias WTH as T

    // ---- epilogue 1 ----
    int u_l = lane >> 2, jc = 2 * (lane & 3);
    int aL = 2 * w, aH = 2 * w + 1;
    int r0 = 16 * w + u_l;
    {
        const float* c1s = (const float*)(smem + OFF_C1);
        const float* c2s = (const float*)(smem + OFF_C2);
        float* sue = (float*)(smem + OFF_UE);
#pragma unroll
        for (int nt = 0; nt < 8; ++nt) {
            int col = nt * 8 + jc;
            float vap0 = frelu(c1s[aL * 64 + col]     + acc[nt][0]);
            float vap1 = frelu(c1s[aL * 64 + col + 1] + acc[nt][1]);
            float vap2 = frelu(c1s[aH * 64 + col]     + acc[nt][2]);
            float vap3 = frelu(c1s[aH * 64 + col + 1] + acc[nt][3]);
            float vue0 = frelu(c2s[u_l * 64 + col]     + acc[nt + 8][0]);
            float vue1 = frelu(c2s[u_l * 64 + col + 1] + acc[nt + 8][1]);
            float vue2 = frelu(c2s[u_l * 64 + col]     + acc[nt + 8][2]);
            float vue3 = frelu(c2s[u_l * 64 + col + 1] + acc[nt + 8][3]);
            // T = -(ap+ue), bf16 hi only (aliases W12h region)
            *(uint32_t*)(smem + OFF_WTH + SWZ(r0 * 128 + col * 2)) =
                pack_bf16(-(vap0 + vue0), -(vap1 + vue1));
            *(uint32_t*)(smem + OFF_WTH + SWZ((r0 + 8) * 128 + col * 2)) =
                pack_bf16(-(vap2 + vue2), -(vap3 + vue3));
            // ue partials into smem (sum over this warp's 2 a's)
            atomicAdd(&sue[u_l * 64 + col],     vue0 + vue2);
            atomicAdd(&sue[u_l * 64 + col + 1], vue1 + vue3);
            // ap sums: butterfly over the 8 u's (lane>>2 axis)
            float s0 = vap0, s1 = vap1, s2 = vap2, s3 = vap3;
#pragma unroll
            for (int d = 4; d < 32; d <<= 1) {
                s0 += __shfl_xor_sync(0xffffffffu, s0, d);
                s1 += __shfl_xor_sync(0xffffffffu, s1, d);
                s2 += __shfl_xor_sync(0xffffffffu, s2, d);
                s3 += __shfl_xor_sync(0xffffffffu, s3, d);
            }
            if (lane < 4) {
                atomicAdd(&g_ap_sum[(a0 + aL) * DD + nt * 8 + 2 * lane],     s0);
                atomicAdd(&g_ap_sum[(a0 + aL) * DD + nt * 8 + 2 * lane + 1], s1);
                atomicAdd(&g_ap_sum[(a0 + aH) * DD + nt * 8 + 2 * lane],     s2);
                atomicAdd(&g_ap_sum[(a0 + aH) * DD + nt * 8 + 2 * lane + 1], s3);
            }
        }
    }
    __syncthreads();  // T complete (cross-lane ldmatrix), sue complete

    // ue cross-block REDs (fire-and-forget, overlaps MMA2 issue)
    {
        const float* sue = (const float*)(smem + OFF_UE);
#pragma unroll
        for (int i = 0; i < 2; ++i) {
            int idx = t + i * 256;
            atomicAdd(&g_ue_sum[(u0 + (idx >> 6)) * DD + (idx & 63)], sue[idx]);
        }
    }

    // ---- MMA2 ----
    float acc2[8][4];
#pragma unroll
    for (int nt = 0; nt < 8; ++nt)
#pragma unroll
        for (int j = 0; j < 4; ++j) acc2[nt][j] = 0.0f;

#pragma unroll
    for (int ks = 0; ks < 8; ++ks) {
        uint32_t srcA = (ks < 4) ? OFF_EH : OFF_WTH;
        uint32_t ah[4];
        int ao = SWZ(arow * 128 + (ks & 3) * 32 + acol);
        ldsm_x4(ah, sb + srcA + ao);
        int brow = ks * 16 + (lane & 15);
#pragma unroll
        for (int nt2 = 0; nt2 < 4; ++nt2) {
            int ntp = 2 * nt2 + ntsel;
            uint32_t boff = (uint32_t)SWZ(brow * 128 + ntp * 16);
            uint32_t bh[4], bl[4];
            ldsm_x4t(bh, sb + OFF_W3H + boff);
            ldsm_x4t(bl, sb + OFF_W3L + boff);
            mma_bf16(acc2[2 * nt2],     ah, bh);
            mma_bf16(acc2[2 * nt2],     ah, bl);
            mma_bf16(acc2[2 * nt2 + 1], ah, bh + 2);
            mma_bf16(acc2[2 * nt2 + 1], ah, bl + 2);
        }
    }
    __syncthreads();  // E/T consumed -> stage output into EH+WTH region (32KB)

    // ---- epilogue 2: stage + coalesced write ----
    {
#pragma unroll
        for (int nt = 0; nt < 8; ++nt) {
            int col = nt * 8 + jc;
            *(float2*)(smem + OFF_EH + SWZO(r0 * 256 + col * 4)) =
                make_float2(acc2[nt][0], acc2[nt][1]);
            *(float2*)(smem + OFF_EH + SWZO((r0 + 8) * 256 + col * 4)) =
                make_float2(acc2[nt][2], acc2[nt][3]);
        }
    }
    __syncthreads();
#pragma unroll
    for (int i = 0; i < 8; ++i) {
        int lin = i * 256 + t;
        int row = lin >> 4, c4 = lin & 15;
        float4 v = *(float4*)(smem + OFF_EH + SWZO(row * 256 + c4 * 16));
        size_t g = ((size_t)(a0 + (row >> 3)) * NU + (u0 + (row & 7))) * DD + c4 * 4;
        *(float4*)&out[g] = v;
    }
}

// ---------------------------------------------------------------------------
// KC: corr_a[a] = ap_sum[a].W3bot ; corr_u[u] = ue_sum[u].W3bot + b3  (fp32)
// ---------------------------------------------------------------------------
__global__ void __launch_bounds__(256) kc_corr(const float* __restrict__ W3,
                                               const float* __restrict__ b3) {
    int row = blockIdx.x * 4 + (threadIdx.x >> 6);
    int d = threadIdx.x & 63;
    const float* S; float* O; float base;
    if (row < NA) { S = g_ap_sum + row * DD; O = g_corr_a + row * DD; base = 0.0f; }
    else { int u = row - NA; S = g_ue_sum + u * DD; O = g_corr_u + u * DD; base = b3[d]; }
    float a0 = base, a1 = 0.0f, a2 = 0.0f, a3 = 0.0f;
#pragma unroll 4
    for (int k = 0; k < DD; k += 4) {
        a0 += S[k]     * W3[(64 + k)     * DD + d];
        a1 += S[k + 1] * W3[(64 + k + 1) * DD + d];
        a2 += S[k + 2] * W3[(64 + k + 2) * DD + d];
        a3 += S[k + 3] * W3[(64 + k + 3) * DD + d];
    }
    O[d] = (a0 + a1) + (a2 + a3);
}

// ---------------------------------------------------------------------------
// KF: out += corr_a[a] + corr_u[u]   (b3 folded into corr_u)
// ---------------------------------------------------------------------------
__global__ void __launch_bounds__(256) kf_final(float* __restrict__ out) {
    int t0 = blockIdx.x * 256 + threadIdx.x;
#pragma unroll
    for (int i = 0; i < 4; ++i) {
        int fi = t0 + i * 1048576;
        int m = fi >> 4;
        int dq = (fi & 15) * 4;
        int a = m >> 10, u = m & 1023;
        float4 o = ((float4*)out)[fi];
        float4 ca = *(const float4*)&g_corr_a[a * DD + dq];
        float4 cu = *(const float4*)&g_corr_u[u * DD + dq];
        o.x += ca.x + cu.x;
        o.y += ca.y + cu.y;
        o.z += ca.z + cu.z;
        o.w += ca.w + cu.w;
        ((float4*)out)[fi] = o;
    }
}

// ---------------------------------------------------------------------------
extern "C" void kernel_launch(void* const* d_in, const int* in_sizes, int n_in,
                              void* d_out, int out_size) {
    const float* ap_hid = (const float*)d_in[0];
    const float* ue_hid = (const float*)d_in[1];
    const float* edge   = (const float*)d_in[2];
    const float* W1     = (const float*)d_in[3];
    const float* b1     = (const float*)d_in[4];
    const float* W2     = (const float*)d_in[5];
    const float* b2     = (const float*)d_in[6];
    const float* W3     = (const float*)d_in[7];
    const float* b3     = (const float*)d_in[8];
    float* out = (float*)d_out;

    cudaFuncSetAttribute(kt_fused, cudaFuncAttributeMaxDynamicSharedMemorySize, SMEM_KT);

    kp_prep<<<320, 256>>>(ap_hid, ue_hid, W1, b1, W2, b2, W3);
    kt_fused<<<2048, 256, SMEM_KT>>>(edge, out);
    kc_corr<<<320, 256>>>(W3, b3);
    kf_final<<<4096, 256>>>(out);
}

// round 16
// speedup vs baseline: 2.0000x; 1.1805x over previous
#include <cuda_runtime.h>
#include <cuda_bf16.h>
#include <cstdint>

#define NA 256
#define NU 1024
#define DD 64
#define NE (NA * NU)

// ---------------- scratch (static __device__, no allocation) ----------------
__device__ __align__(16) float g_ap_sum[NA * DD];
__device__ __align__(16) float g_ue_sum[NU * DD];
__device__ __align__(16) float g_c1[NA * DD];
__device__ __align__(16) float g_c2[NU * DD];
__device__ __align__(16) float g_corr_a[NA * DD];
__device__ __align__(16) float g_corr_u[NU * DD];
// single-term bf16 (rn) weight blobs in ldmatrix-ready swizzled layouts
__device__ __align__(16) unsigned char g_w12[16384];  // [half][k 0..63][n 0..63]
__device__ __align__(16) unsigned char g_w3[16384];   // [k 0..127][n 0..63]

#define SWZ(x)  ((x) ^ (((x) >> 3) & 0x70))   // 128B-row swizzle
#define SWZO(x) ((x) ^ (((x) >> 4) & 0x70))   // 256B-row swizzle (fp32 out staging)

// smem layout (bytes) — pure bf16 operands, fp32 rank-1 correction outside
#define OFF_EH   0        // E bf16 [128][64]  (aliased by out staging later)
#define OFF_WT   16384    // W12 during MMA1 -> T bf16 after
#define OFF_W3   32768
#define OFF_C1   49152    // 16*64 f32
#define OFF_C2   53248    // 8*64 f32
#define OFF_UE   55296    // 8*64 f32 partial ue sums
#define SMEM_KT  57344

// ---------------- helpers ----------------
__device__ __forceinline__ uint32_t smem_u32(const void* p) {
    uint32_t a;
    asm("{ .reg .u64 t; cvta.to.shared.u64 t, %1; cvt.u32.u64 %0, t; }" : "=r"(a) : "l"(p));
    return a;
}
__device__ __forceinline__ void ldsm_x4(uint32_t* r, uint32_t addr) {
    asm volatile("ldmatrix.sync.aligned.m8n8.x4.shared.b16 {%0,%1,%2,%3}, [%4];"
                 : "=r"(r[0]), "=r"(r[1]), "=r"(r[2]), "=r"(r[3]) : "r"(addr));
}
__device__ __forceinline__ void ldsm_x4t(uint32_t* r, uint32_t addr) {
    asm volatile("ldmatrix.sync.aligned.m8n8.x4.trans.shared.b16 {%0,%1,%2,%3}, [%4];"
                 : "=r"(r[0]), "=r"(r[1]), "=r"(r[2]), "=r"(r[3]) : "r"(addr));
}
__device__ __forceinline__ void mma_bf16(float* c, const uint32_t* a, const uint32_t* b) {
    asm volatile("mma.sync.aligned.m16n8k16.row.col.f32.bf16.bf16.f32 "
                 "{%0,%1,%2,%3},{%4,%5,%6,%7},{%8,%9},{%0,%1,%2,%3};"
                 : "+f"(c[0]), "+f"(c[1]), "+f"(c[2]), "+f"(c[3])
                 : "r"(a[0]), "r"(a[1]), "r"(a[2]), "r"(a[3]), "r"(b[0]), "r"(b[1]));
}
__device__ __forceinline__ uint32_t pack_bf16(float a, float b) {
    __nv_bfloat162 v = __float22bfloat162_rn(make_float2(a, b));  // low=a, high=b
    return *(uint32_t*)&v;
}
__device__ __forceinline__ float frelu(float x) { return fmaxf(x, 0.0f); }

// ---------------------------------------------------------------------------
// KP: merged prep. 320 blocks x 256 threads = 81920 threads.
//   - zero ap_sum/ue_sum
//   - c1[a] = b1 + ap_hid[a].W1top ; c2[u] = b2 + ue_hid[u].W2top  (fp32)
//   - build bf16(rn) swizzled weight blobs
// ---------------------------------------------------------------------------
__global__ void __launch_bounds__(256) kp_prep(
    const float* __restrict__ ap_hid, const float* __restrict__ ue_hid,
    const float* __restrict__ W1, const float* __restrict__ b1,
    const float* __restrict__ W2, const float* __restrict__ b2,
    const float* __restrict__ W3) {
    int id = blockIdx.x * 256 + threadIdx.x;   // 0..81919

    // zero sums (81920 == (NA+NU)*DD exactly)
    if (id < NA * DD) g_ap_sum[id] = 0.0f;
    else g_ue_sum[id - NA * DD] = 0.0f;

    // c1/c2 (ILP-4 accumulators)
    {
        int row = id >> 6, d = id & 63;
        const float *H, *W, *B; float* O;
        if (row < NA) { H = ap_hid + row * DD; W = W1; B = b1; O = g_c1 + row * DD; }
        else { int u = row - NA; H = ue_hid + u * DD; W = W2; B = b2; O = g_c2 + u * DD; }
        float a0 = B[d], a1 = 0.0f, a2 = 0.0f, a3 = 0.0f;
#pragma unroll 4
        for (int k = 0; k < DD; k += 4) {
            a0 += H[k]     * W[(k)     * DD + d];
            a1 += H[k + 1] * W[(k + 1) * DD + d];
            a2 += H[k + 2] * W[(k + 2) * DD + d];
            a3 += H[k + 3] * W[(k + 3) * DD + d];
        }
        O[d] = (a0 + a1) + (a2 + a3);
    }

    // weight blobs (bf16 rn, single term)
    if (id < 8192) {                 // W12: [half][k][n], k = bottom rows 64..127
        int h = id >> 12;            // 0=ap(W1), 1=ue(W2)
        int r = id & 4095;
        int k = r >> 6, n = r & 63;
        float f = h ? W2[(64 + k) * DD + n] : W1[(64 + k) * DD + n];
        *(unsigned short*)(g_w12 + h * 8192 + SWZ(k * 128 + n * 2)) =
            __bfloat16_as_ushort(__float2bfloat16(f));
    } else if (id < 16384) {         // W3: [k 0..127][n]
        int e = id - 8192;
        int k = e >> 6, n = e & 63;
        *(unsigned short*)(g_w3 + SWZ(k * 128 + n * 2)) =
            __bfloat16_as_ushort(__float2bfloat16(W3[k * DD + n]));
    }
}

// ---------------------------------------------------------------------------
// KT: fused mma.sync kernel. 2048 blocks, ONE 16a x 8u tile each.
// Pure bf16 MMA operands; fp32 rank-1 correction handled by kc/kf.
//   MMA1: C[128x128] = E . [W1bot|W2bot]        (64 mma/warp)
//   epi1: ap=relu(c1+Cap), ue=relu(c2+Cue); T=-(ap+ue) -> bf16 (WT region);
//         ap_sum via shfl-butterfly + REDG; ue_sum via smem partials + REDG
//   MMA2: D[128x64] = [E|T] . W3               (64 mma/warp) -> staged out
// ---------------------------------------------------------------------------
__global__ void __launch_bounds__(256, 2) kt_fused(const float* __restrict__ edge,
                                                   float* __restrict__ out) {
    extern __shared__ char smem[];
    uint32_t sb = smem_u32(smem);
    int t = threadIdx.x, w = t >> 5, lane = t & 31;
    int at = blockIdx.x >> 7, ut = blockIdx.x & 127;
    int a0 = at * 16, u0 = ut * 8;

    // zero ue partials
    ((float*)(smem + OFF_UE))[t] = 0.0f;
    ((float*)(smem + OFF_UE))[t + 256] = 0.0f;
    // c1/c2 slices
#pragma unroll
    for (int i = 0; i < 4; ++i)
        ((float*)(smem + OFF_C1))[i * 256 + t] = g_c1[a0 * DD + i * 256 + t];
    ((float*)(smem + OFF_C2))[t] = g_c2[u0 * DD + t];
    ((float*)(smem + OFF_C2))[t + 256] = g_c2[u0 * DD + t + 256];
    // weight blobs (already swizzled) — straight float4 copies
#pragma unroll
    for (int i = 0; i < 4; ++i) {
        int idx = i * 256 + t;
        ((float4*)(smem + OFF_WT))[idx] = ((const float4*)g_w12)[idx];
        ((float4*)(smem + OFF_W3))[idx] = ((const float4*)g_w3)[idx];
    }
    // edge tile: fp32 -> bf16 rn, swizzled
#pragma unroll
    for (int i = 0; i < 8; ++i) {
        int lin = i * 256 + t;          // float4 index
        int row = lin >> 4, c4 = lin & 15;
        size_t g = ((size_t)(a0 + (row >> 3)) * NU + (u0 + (row & 7))) * DD + c4 * 4;
        float4 v = *(const float4*)&edge[g];
        int so = SWZ(row * 128 + c4 * 8);
        *(uint2*)(smem + OFF_EH + so) = make_uint2(pack_bf16(v.x, v.y), pack_bf16(v.z, v.w));
    }
    __syncthreads();

    int arow = 16 * w + (lane & 15);
    int acol = (lane >> 4) * 16;        // byte col of A k-tile half
    int ntsel = lane >> 4;              // 0/1: which of the 2 x4t n-tiles this lane addresses

    // ---- MMA1 ----
    float acc[16][4];
#pragma unroll
    for (int nt = 0; nt < 16; ++nt)
#pragma unroll
        for (int j = 0; j < 4; ++j) acc[nt][j] = 0.0f;

#pragma unroll
    for (int ks = 0; ks < 4; ++ks) {
        uint32_t ah[4];
        int ao = SWZ(arow * 128 + ks * 32 + acol);
        ldsm_x4(ah, sb + OFF_EH + ao);
        int brow = ks * 16 + (lane & 15);
#pragma unroll
        for (int nt2 = 0; nt2 < 8; ++nt2) {
            int ntp = 2 * nt2 + ntsel;   // per-lane n-tile index for x4t
            uint32_t boff = (uint32_t)((ntp >> 3) * 8192 + SWZ(brow * 128 + (ntp & 7) * 16));
            uint32_t bw[4];
            ldsm_x4t(bw, sb + OFF_WT + boff);
            mma_bf16(acc[2 * nt2],     ah, bw);
            mma_bf16(acc[2 * nt2 + 1], ah, bw + 2);
        }
    }
    __syncthreads();  // W12 fully consumed -> safe to alias WT as T

    // ---- epilogue 1 ----
    int u_l = lane >> 2, jc = 2 * (lane & 3);
    int aL = 2 * w, aH = 2 * w + 1;
    int r0 = 16 * w + u_l;
    {
        const float* c1s = (const float*)(smem + OFF_C1);
        const float* c2s = (const float*)(smem + OFF_C2);
        float* sue = (float*)(smem + OFF_UE);
#pragma unroll
        for (int nt = 0; nt < 8; ++nt) {
            int col = nt * 8 + jc;
            float vap0 = frelu(c1s[aL * 64 + col]     + acc[nt][0]);
            float vap1 = frelu(c1s[aL * 64 + col + 1] + acc[nt][1]);
            float vap2 = frelu(c1s[aH * 64 + col]     + acc[nt][2]);
            float vap3 = frelu(c1s[aH * 64 + col + 1] + acc[nt][3]);
            float vue0 = frelu(c2s[u_l * 64 + col]     + acc[nt + 8][0]);
            float vue1 = frelu(c2s[u_l * 64 + col + 1] + acc[nt + 8][1]);
            float vue2 = frelu(c2s[u_l * 64 + col]     + acc[nt + 8][2]);
            float vue3 = frelu(c2s[u_l * 64 + col + 1] + acc[nt + 8][3]);
            // T = -(ap+ue), bf16 rn (aliases W12 region)
            *(uint32_t*)(smem + OFF_WT + SWZ(r0 * 128 + col * 2)) =
                pack_bf16(-(vap0 + vue0), -(vap1 + vue1));
            *(uint32_t*)(smem + OFF_WT + SWZ((r0 + 8) * 128 + col * 2)) =
                pack_bf16(-(vap2 + vue2), -(vap3 + vue3));
            // ue partials into smem (sum over this warp's 2 a's)
            atomicAdd(&sue[u_l * 64 + col],     vue0 + vue2);
            atomicAdd(&sue[u_l * 64 + col + 1], vue1 + vue3);
            // ap sums: butterfly over the 8 u's (lane>>2 axis)
            float s0 = vap0, s1 = vap1, s2 = vap2, s3 = vap3;
#pragma unroll
            for (int d = 4; d < 32; d <<= 1) {
                s0 += __shfl_xor_sync(0xffffffffu, s0, d);
                s1 += __shfl_xor_sync(0xffffffffu, s1, d);
                s2 += __shfl_xor_sync(0xffffffffu, s2, d);
                s3 += __shfl_xor_sync(0xffffffffu, s3, d);
            }
            if (lane < 4) {
                atomicAdd(&g_ap_sum[(a0 + aL) * DD + nt * 8 + 2 * lane],     s0);
                atomicAdd(&g_ap_sum[(a0 + aL) * DD + nt * 8 + 2 * lane + 1], s1);
                atomicAdd(&g_ap_sum[(a0 + aH) * DD + nt * 8 + 2 * lane],     s2);
                atomicAdd(&g_ap_sum[(a0 + aH) * DD + nt * 8 + 2 * lane + 1], s3);
            }
        }
    }
    __syncthreads();  // T complete (cross-lane ldmatrix), sue complete

    // ue cross-block REDs (fire-and-forget, overlaps MMA2 issue)
    {
        const float* sue = (const float*)(smem + OFF_UE);
#pragma unroll
        for (int i = 0; i < 2; ++i) {
            int idx = t + i * 256;
            atomicAdd(&g_ue_sum[(u0 + (idx >> 6)) * DD + (idx & 63)], sue[idx]);
        }
    }

    // ---- MMA2 ----
    float acc2[8][4];
#pragma unroll
    for (int nt = 0; nt < 8; ++nt)
#pragma unroll
        for (int j = 0; j < 4; ++j) acc2[nt][j] = 0.0f;

#pragma unroll
    for (int ks = 0; ks < 8; ++ks) {
        uint32_t srcA = (ks < 4) ? OFF_EH : OFF_WT;
        uint32_t ah[4];
        int ao = SWZ(arow * 128 + (ks & 3) * 32 + acol);
        ldsm_x4(ah, sb + srcA + ao);
        int brow = ks * 16 + (lane & 15);
#pragma unroll
        for (int nt2 = 0; nt2 < 4; ++nt2) {
            int ntp = 2 * nt2 + ntsel;
            uint32_t boff = (uint32_t)SWZ(brow * 128 + ntp * 16);
            uint32_t bw[4];
            ldsm_x4t(bw, sb + OFF_W3 + boff);
            mma_bf16(acc2[2 * nt2],     ah, bw);
            mma_bf16(acc2[2 * nt2 + 1], ah, bw + 2);
        }
    }
    __syncthreads();  // E/T consumed -> stage output into EH+WT region (32KB)

    // ---- epilogue 2: stage + coalesced write ----
    {
#pragma unroll
        for (int nt = 0; nt < 8; ++nt) {
            int col = nt * 8 + jc;
            *(float2*)(smem + OFF_EH + SWZO(r0 * 256 + col * 4)) =
                make_float2(acc2[nt][0], acc2[nt][1]);
            *(float2*)(smem + OFF_EH + SWZO((r0 + 8) * 256 + col * 4)) =
                make_float2(acc2[nt][2], acc2[nt][3]);
        }
    }
    __syncthreads();
#pragma unroll
    for (int i = 0; i < 8; ++i) {
        int lin = i * 256 + t;
        int row = lin >> 4, c4 = lin & 15;
        float4 v = *(float4*)(smem + OFF_EH + SWZO(row * 256 + c4 * 16));
        size_t g = ((size_t)(a0 + (row >> 3)) * NU + (u0 + (row & 7))) * DD + c4 * 4;
        *(float4*)&out[g] = v;
    }
}

// ---------------------------------------------------------------------------
// KC: corr_a[a] = ap_sum[a].W3bot ; corr_u[u] = ue_sum[u].W3bot + b3  (fp32)
// ---------------------------------------------------------------------------
__global__ void __launch_bounds__(256) kc_corr(const float* __restrict__ W3,
                                               const float* __restrict__ b3) {
    int row = blockIdx.x * 4 + (threadIdx.x >> 6);
    int d = threadIdx.x & 63;
    const float* S; float* O; float base;
    if (row < NA) { S = g_ap_sum + row * DD; O = g_corr_a + row * DD; base = 0.0f; }
    else { int u = row - NA; S = g_ue_sum + u * DD; O = g_corr_u + u * DD; base = b3[d]; }
    float a0 = base, a1 = 0.0f, a2 = 0.0f, a3 = 0.0f;
#pragma unroll 4
    for (int k = 0; k < DD; k += 4) {
        a0 += S[k]     * W3[(64 + k)     * DD + d];
        a1 += S[k + 1] * W3[(64 + k + 1) * DD + d];
        a2 += S[k + 2] * W3[(64 + k + 2) * DD + d];
        a3 += S[k + 3] * W3[(64 + k + 3) * DD + d];
    }
    O[d] = (a0 + a1) + (a2 + a3);
}

// ---------------------------------------------------------------------------
// KF: out += corr_a[a] + corr_u[u]   (b3 folded into corr_u)
// ---------------------------------------------------------------------------
__global__ void __launch_bounds__(256) kf_final(float* __restrict__ out) {
    int t0 = blockIdx.x * 256 + threadIdx.x;
#pragma unroll
    for (int i = 0; i < 4; ++i) {
        int fi = t0 + i * 1048576;
        int m = fi >> 4;
        int dq = (fi & 15) * 4;
        int a = m >> 10, u = m & 1023;
        float4 o = ((float4*)out)[fi];
        float4 ca = *(const float4*)&g_corr_a[a * DD + dq];
        float4 cu = *(const float4*)&g_corr_u[u * DD + dq];
        o.x += ca.x + cu.x;
        o.y += ca.y + cu.y;
        o.z += ca.z + cu.z;
        o.w += ca.w + cu.w;
        ((float4*)out)[fi] = o;
    }
}

// ---------------------------------------------------------------------------
extern "C" void kernel_launch(void* const* d_in, const int* in_sizes, int n_in,
                              void* d_out, int out_size) {
    const float* ap_hid = (const float*)d_in[0];
    const float* ue_hid = (const float*)d_in[1];
    const float* edge   = (const float*)d_in[2];
    const float* W1     = (const float*)d_in[3];
    const float* b1     = (const float*)d_in[4];
    const float* W2     = (const float*)d_in[5];
    const float* b2     = (const float*)d_in[6];
    const float* W3     = (const float*)d_in[7];
    const float* b3     = (const float*)d_in[8];
    float* out = (float*)d_out;

    cudaFuncSetAttribute(kt_fused, cudaFuncAttributeMaxDynamicSharedMemorySize, SMEM_KT);

    kp_prep<<<320, 256>>>(ap_hid, ue_hid, W1, b1, W2, b2, W3);
    kt_fused<<<2048, 256, SMEM_KT>>>(edge, out);
    kc_corr<<<320, 256>>>(W3, b3);
    kf_final<<<4096, 256>>>(out);
}